// round 14
// baseline (speedup 1.0000x reference)
#include <cuda_runtime.h>
#include <cuda_bf16.h>
#include <math.h>
#include <stdint.h>

#define BB 8
#define TT 1024
#define VV 2048
#define NBLK 288

// Scratch (__device__ globals: allocation-free rule)
__device__ __nv_bfloat16 g_Ebf[TT];            // bf16-rounded exp(vw[d])
__device__ float         g_Sinv[TT];           // 1 / prefix_sum(round_bf16(exp(vw)))
__device__ __nv_bfloat16 g_M[BB][TT][TT];      // bf16(W[idx_t][idx_s'])   (16MB)
__device__ __nv_bfloat16 g_a2h[BB][TT][TT];    // pre-softmax scores, bf16 (16MB)

// Grid barrier state (zero-initialized at module load; returns to count=0 after
// every launch, phase is a monotonic generation counter -> replay-safe).
__device__ unsigned g_barCount;
__device__ unsigned g_barPhase;

__device__ __forceinline__ void grid_sync() {
    __threadfence();
    __syncthreads();
    if (threadIdx.x == 0) {
        unsigned old = atomicAdd(&g_barPhase, 0u);
        if (atomicAdd(&g_barCount, 1u) == NBLK - 1) {
            g_barCount = 0u;
            __threadfence();
            atomicAdd(&g_barPhase, 1u);
        } else {
            while (atomicAdd(&g_barPhase, 0u) == old) { }
        }
        __threadfence();
    }
    __syncthreads();
}

__device__ __forceinline__ uint32_t smem_u32(const void* p) {
    return (uint32_t)__cvta_generic_to_shared(p);
}
__device__ __forceinline__ void cp16(uint32_t dst, const void* src) {
    asm volatile("cp.async.ca.shared.global [%0], [%1], 16;\n" :: "r"(dst), "l"(src));
}
__device__ __forceinline__ float exp_poly(float x) {
    return 1.0f + x * (1.0f + x * (0.5f + x * (0.16666667f + x * 0.041666667f)));
}
__device__ __forceinline__ void bar_g(int id) {
    asm volatile("bar.sync %0, 128;" :: "r"(id + 1) : "memory");
}

// Shared memory plan (35.5 KB, aliased per phase):
//  gather: rows[2][VV] f32 @0 (16KB) | sidx[TT] @16384 (4KB) | wsum @20480
//  gemm:   Ab[2][8192] @0 (16KB) | Bb[2][8192] @16384 (16KB) | sE @32768 (2KB) | sSinv @34816
//  out:    sacc[2][VV] @0 (16KB) | sidx @16384 (4KB) | sred @20480
#define SMEM_BYTES 35456

__global__ __launch_bounds__(256, 2) void k_fused(const int* __restrict__ idx,
                                                  const float* __restrict__ W,
                                                  const float* __restrict__ vw,
                                                  float* __restrict__ out) {
    __shared__ __align__(16) unsigned char SM[SMEM_BYTES];

    int tid  = threadIdx.x;
    int g    = tid >> 7;                  // group 0..1 (phases 1,3)
    int gt   = tid & 127;
    int wid  = tid >> 5;
    int lane = tid & 31;

    // =====================================================================
    // PHASE 1: E/Sinv (block 0) + gather M = bf16(W[idx_t][idx_s'])
    // =====================================================================
    {
        float (*rows)[VV] = (float(*)[VV])SM;
        int*   sidx = (int*)(SM + 16384);
        float* wsum = (float*)(SM + 20480);

        if (blockIdx.x == 0) {
            int i0 = tid * 4;
            float4 v = *(const float4*)(vw + i0);
            __nv_bfloat16 e0 = __float2bfloat16(expf(v.x));
            __nv_bfloat16 e1 = __float2bfloat16(expf(v.y));
            __nv_bfloat16 e2 = __float2bfloat16(expf(v.z));
            __nv_bfloat16 e3 = __float2bfloat16(expf(v.w));
            union { __nv_bfloat16 h[4]; uint2 u; } pe;
            pe.h[0] = e0; pe.h[1] = e1; pe.h[2] = e2; pe.h[3] = e3;
            *(uint2*)&g_Ebf[i0] = pe.u;
            float c0 = __bfloat162float(e0);
            float c1 = c0 + __bfloat162float(e1);
            float c2 = c1 + __bfloat162float(e2);
            float c3 = c2 + __bfloat162float(e3);
            float sv = c3;
#pragma unroll
            for (int o = 1; o < 32; o <<= 1) {
                float y = __shfl_up_sync(0xffffffff, sv, o);
                if (lane >= o) sv += y;
            }
            float warpExcl = sv - c3;
            if (lane == 31) wsum[wid] = sv;
            __syncthreads();
            if (wid == 0 && lane < 8) {
                float v8 = wsum[lane];
#pragma unroll
                for (int o = 1; o < 8; o <<= 1) {
                    float y = __shfl_up_sync(0xff, v8, o);
                    if (lane >= o) v8 += y;
                }
                wsum[lane] = v8;
            }
            __syncthreads();
            float base = ((wid > 0) ? wsum[wid - 1] : 0.0f) + warpExcl;
            g_Sinv[i0 + 0] = 1.0f / (base + c0);
            g_Sinv[i0 + 1] = 1.0f / (base + c1);
            g_Sinv[i0 + 2] = 1.0f / (base + c2);
            g_Sinv[i0 + 3] = 1.0f / (base + c3);
            __syncthreads();
        }

        for (int c = blockIdx.x; c < 4096; c += NBLK) {
            int b = c >> 9;
            int t = (c & 511) * 2 + g;

            ((int4*)sidx)[tid] = ((const int4*)(idx + b * TT))[tid];
            int wr = idx[b * TT + t];
            const float4* src = (const float4*)(W + (size_t)wr * VV);
            float4* rdst = (float4*)rows[g];
#pragma unroll
            for (int j = 0; j < 4; j++) rdst[gt + j * 128] = src[gt + j * 128];
            __syncthreads();

            const float* row = rows[g];
            int p0 = gt * 8;
            int4 iv0 = *(const int4*)&sidx[p0];
            int4 iv1 = *(const int4*)&sidx[p0 + 4];
            union { __nv_bfloat162 h2[4]; uint4 u; } pk;
            pk.h2[0] = __floats2bfloat162_rn(row[iv0.x], row[iv0.y]);
            pk.h2[1] = __floats2bfloat162_rn(row[iv0.z], row[iv0.w]);
            pk.h2[2] = __floats2bfloat162_rn(row[iv1.x], row[iv1.y]);
            pk.h2[3] = __floats2bfloat162_rn(row[iv1.z], row[iv1.w]);
            *(uint4*)&g_M[b][t][p0] = pk.u;
            __syncthreads();
        }
    }

    grid_sync();

    // =====================================================================
    // PHASE 2: bf16 MMA GEMM, TK=32, 2-stage cp.async, heavy-light mapping
    //   a2[b][t][s] = Sinv[s] * sum_{k<=s} M[t,k] * E[s-k] -> bf16
    // =====================================================================
    {
        unsigned char* Ab = SM;                          // [2][8192]
        unsigned char* Bb = SM + 16384;                  // [2][8192]
        __nv_bfloat16* sE = (__nv_bfloat16*)(SM + 32768);
        float* sSinv = (float*)(SM + 34816);

        int r = blockIdx.x;                              // 0..287
        int k = (r < 144) ? (2 * r) : (2 * (287 - r) + 1);
        int si, off;
        if      (k <   8) { si = 7; off = 0;   }
        else if (k <  24) { si = 6; off = 8;   }
        else if (k <  48) { si = 5; off = 24;  }
        else if (k <  80) { si = 4; off = 48;  }
        else if (k < 120) { si = 3; off = 80;  }
        else if (k < 168) { si = 2; off = 120; }
        else if (k < 224) { si = 1; off = 168; }
        else              { si = 0; off = 224; }
        int m  = k - off;
        int ti = si + (m >> 3);
        int b  = m & 7;
        int t0 = ti * 128;
        int s0 = si * 128;

        int m_base = (wid >> 1) * 32;
        int n_base = (wid & 1) * 64;

        {
            const uint2* esrc = (const uint2*)g_Ebf;
            uint2* edst = (uint2*)sE;
            for (int i = tid; i < TT / 4; i += 256) edst[i] = esrc[i];
            if (tid < 128) sSinv[tid] = g_Sinv[s0 + tid];
        }

        float acc[2][8][4];
#pragma unroll
        for (int mi = 0; mi < 2; mi++)
#pragma unroll
            for (int nj = 0; nj < 8; nj++)
#pragma unroll
                for (int q = 0; q < 4; q++) acc[mi][nj][q] = 0.0f;

        int a_row = tid >> 1;
        int a_v0  = (tid & 1) * 2;
        int b_k   = tid >> 4;
        int b_vn  = tid & 15;
        int nsteps = (s0 + 128) >> 5;     // TK=32

        auto issueA = [&](int stage, int k0) {
#pragma unroll
            for (int vv = 0; vv < 2; vv++) {
                int v = a_v0 + vv;
                uint32_t dst = smem_u32(Ab + stage * 8192 + a_row * 64 + ((v ^ (a_row & 3)) * 16));
                cp16(dst, &g_M[b][t0 + a_row][k0 + v * 8]);
            }
            asm volatile("cp.async.commit_group;\n");
        };
        auto issueB = [&](int stage, int k0) {
#pragma unroll
            for (int rr2 = 0; rr2 < 2; rr2++) {
                int rr = b_k + rr2 * 16;
                union { __nv_bfloat16 h[8]; uint4 u; } pk;
                int dbase = (s0 + b_vn * 8) - (k0 + rr);
#pragma unroll
                for (int j = 0; j < 8; j++) {
                    int d = dbase + j;
                    pk.h[j] = (d >= 0) ? sE[d] : __float2bfloat16(0.0f);
                }
                *(uint4*)(Bb + stage * 8192 + rr * 256 + ((b_vn ^ (rr & 7)) * 16)) = pk.u;
            }
        };

        __syncthreads();
        issueA(0, 0);
        issueB(0, 0);

        for (int step = 0; step < nsteps; step++) {
            int stage = step & 1;
            asm volatile("cp.async.wait_group 0;\n");
            __syncthreads();

            if (step + 1 < nsteps) {
                issueA(stage ^ 1, (step + 1) * 32);
                issueB(stage ^ 1, (step + 1) * 32);
            }

#pragma unroll
            for (int kc = 0; kc < 32; kc += 16) {
                uint32_t afr[2][4];
#pragma unroll
                for (int mi = 0; mi < 2; mi++) {
                    int row = m_base + mi * 16 + (lane & 15);
                    int v   = (kc >> 3) + (lane >> 4);
                    uint32_t addr = smem_u32(Ab + stage * 8192 + row * 64 + ((v ^ (row & 3)) * 16));
                    asm volatile("ldmatrix.sync.aligned.m8n8.x4.shared.b16 {%0,%1,%2,%3}, [%4];"
                                 : "=r"(afr[mi][0]), "=r"(afr[mi][1]),
                                   "=r"(afr[mi][2]), "=r"(afr[mi][3])
                                 : "r"(addr));
                }
                uint32_t bfr[8][2];
#pragma unroll
                for (int nj2 = 0; nj2 < 4; nj2++) {
                    int nvec = (n_base >> 3) + nj2 * 2 + (lane >> 4);
                    int krow = kc + (lane & 15);
                    uint32_t addr = smem_u32(Bb + stage * 8192 + krow * 256 + ((nvec ^ (krow & 7)) * 16));
                    uint32_t q0, q1, q2, q3;
                    asm volatile("ldmatrix.sync.aligned.m8n8.x4.trans.shared.b16 {%0,%1,%2,%3}, [%4];"
                                 : "=r"(q0), "=r"(q1), "=r"(q2), "=r"(q3)
                                 : "r"(addr));
                    bfr[nj2 * 2 + 0][0] = q0; bfr[nj2 * 2 + 0][1] = q1;
                    bfr[nj2 * 2 + 1][0] = q2; bfr[nj2 * 2 + 1][1] = q3;
                }
#pragma unroll
                for (int mi = 0; mi < 2; mi++)
#pragma unroll
                    for (int nj = 0; nj < 8; nj++) {
                        asm volatile(
                            "mma.sync.aligned.m16n8k16.row.col.f32.bf16.bf16.f32 "
                            "{%0,%1,%2,%3}, {%4,%5,%6,%7}, {%8,%9}, {%0,%1,%2,%3};"
                            : "+f"(acc[mi][nj][0]), "+f"(acc[mi][nj][1]),
                              "+f"(acc[mi][nj][2]), "+f"(acc[mi][nj][3])
                            : "r"(afr[mi][0]), "r"(afr[mi][1]), "r"(afr[mi][2]), "r"(afr[mi][3]),
                              "r"(bfr[nj][0]), "r"(bfr[nj][1]));
                    }
            }
        }

        // m16n8k16 D-fragment: c0,c1 -> (row, col/col+1); c2,c3 -> (row+8, ...)
#pragma unroll
        for (int mi = 0; mi < 2; mi++) {
#pragma unroll
            for (int nj = 0; nj < 8; nj++) {
                int row0 = m_base + mi * 16 + (lane >> 2);
                int col  = n_base + nj * 8 + (lane & 3) * 2;
                float si0 = sSinv[col];
                float si1 = sSinv[col + 1];
                __nv_bfloat162 h0 = __floats2bfloat162_rn(acc[mi][nj][0] * si0,
                                                          acc[mi][nj][1] * si1);
                __nv_bfloat162 h1 = __floats2bfloat162_rn(acc[mi][nj][2] * si0,
                                                          acc[mi][nj][3] * si1);
                *(__nv_bfloat162*)&g_a2h[b][t0 + row0][s0 + col]     = h0;
                *(__nv_bfloat162*)&g_a2h[b][t0 + row0 + 8][s0 + col] = h1;
            }
        }
    }

    grid_sync();

    // =====================================================================
    // PHASE 3: softmax + scatter + output store (2 rows per iteration)
    // =====================================================================
    {
        float* sacc = (float*)SM;                 // [2][VV]
        int*   sidx = (int*)(SM + 16384);
        float* sred = (float*)(SM + 20480);       // [2][4]

        for (int c = blockIdx.x; c < 4096; c += NBLK) {
            int b = c >> 9;
            int t = (c & 511) * 2 + g;
            int n = t + 1;

            ((int4*)sidx)[tid] = ((const int4*)(idx + b * TT))[tid];
            {
                float4* z = (float4*)(sacc + g * VV);
#pragma unroll
                for (int j = 0; j < 4; j++) z[gt + j * 128] = make_float4(0.f, 0.f, 0.f, 0.f);
            }
            __syncthreads();

            const __nv_bfloat16* row = &g_a2h[b][t][0];
            float pv[8];
            float sum = 0.0f;
#pragma unroll
            for (int j = 0; j < 8; j++) {
                int s = gt + j * 128;
                float e = 0.0f;
                if (s < n) e = exp_poly(__bfloat162float(row[s]));
                pv[j] = e;
                sum += e;
            }
#pragma unroll
            for (int o = 16; o > 0; o >>= 1)
                sum += __shfl_xor_sync(0xffffffff, sum, o);
            if ((gt & 31) == 0) sred[g * 4 + (gt >> 5)] = sum;
            bar_g(g);
            float inv = 1.0f / (sred[g * 4 + 0] + sred[g * 4 + 1] +
                                sred[g * 4 + 2] + sred[g * 4 + 3]);

#pragma unroll
            for (int j = 0; j < 8; j++) {
                int s = gt + j * 128;
                if (s < n) atomicAdd(&sacc[g * VV + sidx[s]], pv[j] * inv);
            }
            bar_g(g);

            float4* dst = (float4*)(out + ((size_t)(b * TT + t)) * VV);
            const float4* src = (const float4*)(sacc + g * VV);
#pragma unroll
            for (int j = 0; j < 4; j++) dst[gt + j * 128] = src[gt + j * 128];
            __syncthreads();
        }
    }
}

// ---------------------------------------------------------------------------
extern "C" void kernel_launch(void* const* d_in, const int* in_sizes, int n_in,
                              void* d_out, int out_size) {
    const int*   idx = nullptr;
    const float* vw  = nullptr;
    const float* W   = nullptr;
    for (int i = 0; i < n_in; i++) {
        if (in_sizes[i] == BB * TT)       idx = (const int*)d_in[i];
        else if (in_sizes[i] == TT)       vw  = (const float*)d_in[i];
        else if (in_sizes[i] == VV * VV)  W   = (const float*)d_in[i];
    }
    float* out = (float*)d_out;

    k_fused<<<NBLK, 256>>>(idx, W, vw, out);
}

// round 15
// speedup vs baseline: 1.2344x; 1.2344x over previous
#include <cuda_runtime.h>
#include <cuda_bf16.h>
#include <math.h>
#include <stdint.h>

#define BB 8
#define TT 1024
#define VV 2048

// Scratch (__device__ globals: allocation-free rule)
__device__ __nv_bfloat16 g_Ebf[TT];            // bf16-rounded exp(vw[d])
__device__ float         g_Sinv[TT];           // 1 / prefix_sum(round_bf16(exp(vw)))
__device__ __nv_bfloat16 g_M[BB][TT][TT];      // bf16(W[idx_t][idx_s'])   (16MB)
__device__ __nv_bfloat16 g_a2h[BB][TT][TT];    // pre-softmax scores, bf16 (16MB)

// ---------------------------------------------------------------------------
// Kernel 1: gather M[b][t][s'] = bf16(W[idx[b,t]][idx[b,s']]).
// 256 threads, 2 rows per block (R12 form, measured 15.9us).
// Block (0,0) also computes E (bf16) + prefix-scan -> g_Ebf, g_Sinv.
// ---------------------------------------------------------------------------
__global__ __launch_bounds__(256) void k_gather(const int* __restrict__ idx,
                                                const float* __restrict__ W,
                                                const float* __restrict__ vw) {
    int b  = blockIdx.y;
    int g  = threadIdx.x >> 7;            // group 0..1
    int gt = threadIdx.x & 127;
    int t  = blockIdx.x * 2 + g;
    int tid = threadIdx.x;

    __shared__ float rows[2][VV];         // 16 KB
    __shared__ int   sidx[TT];            // 4 KB
    __shared__ float wsum[8];

    ((int4*)sidx)[tid] = ((const int4*)(idx + b * TT))[tid];

    int wr = idx[b * TT + t];
    const float4* src = (const float4*)(W + (size_t)wr * VV);
    float4* rdst = (float4*)rows[g];
#pragma unroll
    for (int j = 0; j < 4; j++) rdst[gt + j * 128] = src[gt + j * 128];

    // ---- prefix fold: only block (0,0) ----
    if (blockIdx.x == 0 && blockIdx.y == 0) {
        int lane = tid & 31, wid = tid >> 5;
        int i0 = tid * 4;
        float4 v = *(const float4*)(vw + i0);
        __nv_bfloat16 e0 = __float2bfloat16(expf(v.x));
        __nv_bfloat16 e1 = __float2bfloat16(expf(v.y));
        __nv_bfloat16 e2 = __float2bfloat16(expf(v.z));
        __nv_bfloat16 e3 = __float2bfloat16(expf(v.w));
        union { __nv_bfloat16 h[4]; uint2 u; } pe;
        pe.h[0] = e0; pe.h[1] = e1; pe.h[2] = e2; pe.h[3] = e3;
        *(uint2*)&g_Ebf[i0] = pe.u;
        float c0 = __bfloat162float(e0);
        float c1 = c0 + __bfloat162float(e1);
        float c2 = c1 + __bfloat162float(e2);
        float c3 = c2 + __bfloat162float(e3);
        float sv = c3;
#pragma unroll
        for (int o = 1; o < 32; o <<= 1) {
            float y = __shfl_up_sync(0xffffffff, sv, o);
            if (lane >= o) sv += y;
        }
        float warpExcl = sv - c3;
        if (lane == 31) wsum[wid] = sv;
        __syncthreads();
        if (wid == 0 && lane < 8) {
            float v8 = wsum[lane];
#pragma unroll
            for (int o = 1; o < 8; o <<= 1) {
                float y = __shfl_up_sync(0xff, v8, o);
                if (lane >= o) v8 += y;
            }
            wsum[lane] = v8;
        }
        __syncthreads();
        float base = ((wid > 0) ? wsum[wid - 1] : 0.0f) + warpExcl;
        g_Sinv[i0 + 0] = 1.0f / (base + c0);
        g_Sinv[i0 + 1] = 1.0f / (base + c1);
        g_Sinv[i0 + 2] = 1.0f / (base + c2);
        g_Sinv[i0 + 3] = 1.0f / (base + c3);
    }
    __syncthreads();

    const float* row = rows[g];
    int p0 = gt * 8;
    int4 iv0 = *(const int4*)&sidx[p0];
    int4 iv1 = *(const int4*)&sidx[p0 + 4];
    union { __nv_bfloat162 h2[4]; uint4 u; } pk;
    pk.h2[0] = __floats2bfloat162_rn(row[iv0.x], row[iv0.y]);
    pk.h2[1] = __floats2bfloat162_rn(row[iv0.z], row[iv0.w]);
    pk.h2[2] = __floats2bfloat162_rn(row[iv1.x], row[iv1.y]);
    pk.h2[3] = __floats2bfloat162_rn(row[iv1.z], row[iv1.w]);
    *(uint4*)&g_M[b][t][p0] = pk.u;
}

// ---------------------------------------------------------------------------
// Kernel 2: bf16 tensor-core GEMM (R10 version, verbatim).
//   a2[b][t][s] = Sinv[s] * sum_{k<=s} M[t,k] * E[s-k]   -> bf16
// ---------------------------------------------------------------------------
__device__ __forceinline__ uint32_t smem_u32(const void* p) {
    return (uint32_t)__cvta_generic_to_shared(p);
}
__device__ __forceinline__ void cp16(uint32_t dst, const void* src) {
    asm volatile("cp.async.ca.shared.global [%0], [%1], 16;\n" :: "r"(dst), "l"(src));
}

__global__ __launch_bounds__(256, 2) void k_gemm() {
    int r = blockIdx.x;                            // 0..287
    int k = (r < 144) ? (2 * r) : (2 * (287 - r) + 1);
    int si, off;
    if      (k <   8) { si = 7; off = 0;   }
    else if (k <  24) { si = 6; off = 8;   }
    else if (k <  48) { si = 5; off = 24;  }
    else if (k <  80) { si = 4; off = 48;  }
    else if (k < 120) { si = 3; off = 80;  }
    else if (k < 168) { si = 2; off = 120; }
    else if (k < 224) { si = 1; off = 168; }
    else              { si = 0; off = 224; }
    int m  = k - off;
    int ti = si + (m >> 3);
    int b  = m & 7;
    int t0 = ti * 128;
    int s0 = si * 128;

    __shared__ __align__(16) unsigned char Ab[2][128 * 64];   // 16 KB
    __shared__ __align__(16) unsigned char Bb[2][32 * 256];   // 16 KB
    __shared__ __nv_bfloat16 sE[TT];                          // 2 KB
    __shared__ float sSinv[128];

    int tid  = threadIdx.x;
    int wid  = tid >> 5;
    int lane = tid & 31;
    int m_base = (wid >> 1) * 32;
    int n_base = (wid & 1) * 64;

    {
        const uint2* esrc = (const uint2*)g_Ebf;
        uint2* edst = (uint2*)sE;
        for (int i = tid; i < TT / 4; i += 256) edst[i] = esrc[i];
        if (tid < 128) sSinv[tid] = g_Sinv[s0 + tid];
    }

    float acc[2][8][4];
#pragma unroll
    for (int mi = 0; mi < 2; mi++)
#pragma unroll
        for (int nj = 0; nj < 8; nj++)
#pragma unroll
            for (int q = 0; q < 4; q++) acc[mi][nj][q] = 0.0f;

    int a_row = tid >> 1;
    int a_v0  = (tid & 1) * 2;
    int b_k   = tid >> 4;
    int b_vn  = tid & 15;
    int nsteps = (s0 + 128) >> 5;         // TK=32

    auto issueA = [&](int stage, int k0) {
#pragma unroll
        for (int vv = 0; vv < 2; vv++) {
            int v = a_v0 + vv;
            uint32_t dst = smem_u32(Ab[stage] + a_row * 64 + ((v ^ (a_row & 3)) * 16));
            cp16(dst, &g_M[b][t0 + a_row][k0 + v * 8]);
        }
        asm volatile("cp.async.commit_group;\n");
    };
    auto issueB = [&](int stage, int k0) {
#pragma unroll
        for (int rr2 = 0; rr2 < 2; rr2++) {
            int rr = b_k + rr2 * 16;
            union { __nv_bfloat16 h[8]; uint4 u; } pk;
            int dbase = (s0 + b_vn * 8) - (k0 + rr);
#pragma unroll
            for (int j = 0; j < 8; j++) {
                int d = dbase + j;
                pk.h[j] = (d >= 0) ? sE[d] : __float2bfloat16(0.0f);
            }
            *(uint4*)(Bb[stage] + rr * 256 + ((b_vn ^ (rr & 7)) * 16)) = pk.u;
        }
    };

    __syncthreads();
    issueA(0, 0);
    issueB(0, 0);

    for (int step = 0; step < nsteps; step++) {
        int stage = step & 1;
        asm volatile("cp.async.wait_group 0;\n");
        __syncthreads();

        if (step + 1 < nsteps) {
            issueA(stage ^ 1, (step + 1) * 32);
            issueB(stage ^ 1, (step + 1) * 32);
        }

#pragma unroll
        for (int kc = 0; kc < 32; kc += 16) {
            uint32_t afr[2][4];
#pragma unroll
            for (int mi = 0; mi < 2; mi++) {
                int row = m_base + mi * 16 + (lane & 15);
                int v   = (kc >> 3) + (lane >> 4);
                uint32_t addr = smem_u32(Ab[stage] + row * 64 + ((v ^ (row & 3)) * 16));
                asm volatile("ldmatrix.sync.aligned.m8n8.x4.shared.b16 {%0,%1,%2,%3}, [%4];"
                             : "=r"(afr[mi][0]), "=r"(afr[mi][1]),
                               "=r"(afr[mi][2]), "=r"(afr[mi][3])
                             : "r"(addr));
            }
            uint32_t bfr[8][2];
#pragma unroll
            for (int nj2 = 0; nj2 < 4; nj2++) {
                int nvec = (n_base >> 3) + nj2 * 2 + (lane >> 4);
                int krow = kc + (lane & 15);
                uint32_t addr = smem_u32(Bb[stage] + krow * 256 + ((nvec ^ (krow & 7)) * 16));
                uint32_t q0, q1, q2, q3;
                asm volatile("ldmatrix.sync.aligned.m8n8.x4.trans.shared.b16 {%0,%1,%2,%3}, [%4];"
                             : "=r"(q0), "=r"(q1), "=r"(q2), "=r"(q3)
                             : "r"(addr));
                bfr[nj2 * 2 + 0][0] = q0; bfr[nj2 * 2 + 0][1] = q1;
                bfr[nj2 * 2 + 1][0] = q2; bfr[nj2 * 2 + 1][1] = q3;
            }
#pragma unroll
            for (int mi = 0; mi < 2; mi++)
#pragma unroll
                for (int nj = 0; nj < 8; nj++) {
                    asm volatile(
                        "mma.sync.aligned.m16n8k16.row.col.f32.bf16.bf16.f32 "
                        "{%0,%1,%2,%3}, {%4,%5,%6,%7}, {%8,%9}, {%0,%1,%2,%3};"
                        : "+f"(acc[mi][nj][0]), "+f"(acc[mi][nj][1]),
                          "+f"(acc[mi][nj][2]), "+f"(acc[mi][nj][3])
                        : "r"(afr[mi][0]), "r"(afr[mi][1]), "r"(afr[mi][2]), "r"(afr[mi][3]),
                          "r"(bfr[nj][0]), "r"(bfr[nj][1]));
                }
        }
    }

    // m16n8k16 D-fragment: c0,c1 -> (row, col/col+1); c2,c3 -> (row+8, col/col+1)
#pragma unroll
    for (int mi = 0; mi < 2; mi++) {
#pragma unroll
        for (int nj = 0; nj < 8; nj++) {
            int row0 = m_base + mi * 16 + (lane >> 2);
            int col  = n_base + nj * 8 + (lane & 3) * 2;
            float si0 = sSinv[col];
            float si1 = sSinv[col + 1];
            __nv_bfloat162 h0 = __floats2bfloat162_rn(acc[mi][nj][0] * si0,
                                                      acc[mi][nj][1] * si1);
            __nv_bfloat162 h1 = __floats2bfloat162_rn(acc[mi][nj][2] * si0,
                                                      acc[mi][nj][3] * si1);
            *(__nv_bfloat162*)&g_a2h[b][t0 + row0][s0 + col]     = h0;
            *(__nv_bfloat162*)&g_a2h[b][t0 + row0 + 8][s0 + col] = h1;
        }
    }
}

// ---------------------------------------------------------------------------
// Kernel 3: softmax + scatter (R10 version, verbatim: 4 rows per block,
// four 128-thread groups with named barriers).
// ---------------------------------------------------------------------------
__device__ __forceinline__ float exp_poly(float x) {
    return 1.0f + x * (1.0f + x * (0.5f + x * (0.16666667f + x * 0.041666667f)));
}
__device__ __forceinline__ void bar_g(int id) {
    asm volatile("bar.sync %0, 128;" :: "r"(id + 1) : "memory");
}

__global__ __launch_bounds__(512) void k_out(const int* __restrict__ idx,
                                             float* __restrict__ out) {
    int b  = blockIdx.y;
    int tb = blockIdx.x * 4;
    int tid = threadIdx.x;
    int g   = tid >> 7;
    int gt  = tid & 127;
    int t   = tb + g;
    int n   = t + 1;

    __shared__ float sacc[4][VV];         // 32 KB
    __shared__ int   sidx[TT];            // 4 KB
    __shared__ float sred[4][4];

    if (tid < 256) ((int4*)sidx)[tid] = ((const int4*)(idx + b * TT))[tid];
    {
        float4* z = (float4*)sacc[g];
#pragma unroll
        for (int j = 0; j < 4; j++) z[gt + j * 128] = make_float4(0.f, 0.f, 0.f, 0.f);
    }
    __syncthreads();

    const __nv_bfloat16* row = &g_a2h[b][t][0];

    float pv[8];
    float sum = 0.0f;
#pragma unroll
    for (int j = 0; j < 8; j++) {
        int s = gt + j * 128;
        float e = 0.0f;
        if (s < n) e = exp_poly(__bfloat162float(row[s]));
        pv[j] = e;
        sum += e;
    }
#pragma unroll
    for (int off = 16; off > 0; off >>= 1)
        sum += __shfl_xor_sync(0xffffffff, sum, off);
    if ((gt & 31) == 0) sred[g][gt >> 5] = sum;
    bar_g(g);
    float inv = 1.0f / (sred[g][0] + sred[g][1] + sred[g][2] + sred[g][3]);

#pragma unroll
    for (int j = 0; j < 8; j++) {
        int s = gt + j * 128;
        if (s < n) atomicAdd(&sacc[g][sidx[s]], pv[j] * inv);
    }
    bar_g(g);

    float4* dst = (float4*)(out + ((size_t)(b * TT + t)) * VV);
    const float4* src = (const float4*)sacc[g];
#pragma unroll
    for (int j = 0; j < 4; j++) dst[gt + j * 128] = src[gt + j * 128];
}

// ---------------------------------------------------------------------------
extern "C" void kernel_launch(void* const* d_in, const int* in_sizes, int n_in,
                              void* d_out, int out_size) {
    const int*   idx = nullptr;
    const float* vw  = nullptr;
    const float* W   = nullptr;
    for (int i = 0; i < n_in; i++) {
        if (in_sizes[i] == BB * TT)       idx = (const int*)d_in[i];
        else if (in_sizes[i] == TT)       vw  = (const float*)d_in[i];
        else if (in_sizes[i] == VV * VV)  W   = (const float*)d_in[i];
    }
    float* out = (float*)d_out;

    dim3 gGather(TT / 2, BB);
    k_gather<<<gGather, 256>>>(idx, W, vw);

    k_gemm<<<288, 256>>>();

    dim3 gOut(TT / 4, BB);
    k_out<<<gOut, 512>>>(idx, out);
}

// round 16
// speedup vs baseline: 1.3033x; 1.0558x over previous
#include <cuda_runtime.h>
#include <cuda_bf16.h>
#include <math.h>
#include <stdint.h>

#define BB 8
#define TT 1024
#define VV 2048

// Scratch (__device__ globals: allocation-free rule)
__device__ __nv_bfloat16 g_Ebf[TT];            // bf16-rounded exp(vw[d])
__device__ float         g_Sinv[TT];           // 1 / prefix_sum(round_bf16(exp(vw)))
__device__ __nv_bfloat16 g_M[BB][TT][TT];      // bf16(W[idx_t][idx_s'])   (16MB)
__device__ __nv_bfloat16 g_a2h[BB][TT][TT];    // pre-softmax scores, bf16 (16MB)

// ---------------------------------------------------------------------------
// Kernel 1: gather M[b][t][s'] = bf16(W[idx[b,t]][idx[b,s']]).
// 128 threads, ONE row per block, 8KB smem -> 16 blocks/SM for latency hiding.
// idx read straight from gmem (L2-hot). Block (0,0) also computes E/Sinv.
// ---------------------------------------------------------------------------
__global__ __launch_bounds__(128) void k_gather(const int* __restrict__ idx,
                                                const float* __restrict__ W,
                                                const float* __restrict__ vw) {
    int b   = blockIdx.y;
    int t   = blockIdx.x;
    int tid = threadIdx.x;

    __shared__ float row[VV];             // 8 KB
    __shared__ float wsum[4];

    // stage the W row (2048 floats = 128 thr x 4 float4)
    int wr = idx[b * TT + t];
    const float4* src = (const float4*)(W + (size_t)wr * VV);
    float4* rdst = (float4*)row;
#pragma unroll
    for (int j = 0; j < 4; j++) rdst[tid + j * 128] = src[tid + j * 128];

    // ---- prefix fold: only block (0,0); 8 vw values per thread ----
    if (blockIdx.x == 0 && blockIdx.y == 0) {
        int lane = tid & 31, wid = tid >> 5;
        int i0 = tid * 8;
        float4 va = *(const float4*)(vw + i0);
        float4 vb = *(const float4*)(vw + i0 + 4);
        float xs[8] = {va.x, va.y, va.z, va.w, vb.x, vb.y, vb.z, vb.w};
        __nv_bfloat16 eb[8];
        float c[8];
        float run = 0.0f;
#pragma unroll
        for (int j = 0; j < 8; j++) {
            eb[j] = __float2bfloat16(expf(xs[j]));
            run += __bfloat162float(eb[j]);
            c[j] = run;
        }
        union { __nv_bfloat16 h[8]; uint4 u; } pe;
#pragma unroll
        for (int j = 0; j < 8; j++) pe.h[j] = eb[j];
        *(uint4*)&g_Ebf[i0] = pe.u;

        float sv = run;                   // warp inclusive scan of per-thread totals
#pragma unroll
        for (int o = 1; o < 32; o <<= 1) {
            float y = __shfl_up_sync(0xffffffff, sv, o);
            if (lane >= o) sv += y;
        }
        float warpExcl = sv - run;
        if (lane == 31) wsum[wid] = sv;
        __syncthreads();
        if (wid == 0 && lane < 4) {
            float v4 = wsum[lane];
#pragma unroll
            for (int o = 1; o < 4; o <<= 1) {
                float y = __shfl_up_sync(0xf, v4, o);
                if (lane >= o) v4 += y;
            }
            wsum[lane] = v4;
        }
        __syncthreads();
        float base = ((wid > 0) ? wsum[wid - 1] : 0.0f) + warpExcl;
#pragma unroll
        for (int j = 0; j < 8; j++) g_Sinv[i0 + j] = 1.0f / (base + c[j]);
    }
    __syncthreads();

    // gather 8 consecutive outputs per thread; idx from gmem (int4 x2)
    int p0 = tid * 8;
    const int4* ig = (const int4*)(idx + b * TT);
    int4 iv0 = ig[tid * 2];
    int4 iv1 = ig[tid * 2 + 1];
    union { __nv_bfloat162 h2[4]; uint4 u; } pk;
    pk.h2[0] = __floats2bfloat162_rn(row[iv0.x], row[iv0.y]);
    pk.h2[1] = __floats2bfloat162_rn(row[iv0.z], row[iv0.w]);
    pk.h2[2] = __floats2bfloat162_rn(row[iv1.x], row[iv1.y]);
    pk.h2[3] = __floats2bfloat162_rn(row[iv1.z], row[iv1.w]);
    *(uint4*)&g_M[b][t][p0] = pk.u;
}

// ---------------------------------------------------------------------------
// Kernel 2: bf16 tensor-core GEMM (R10/R15 version, verbatim).
//   a2[b][t][s] = Sinv[s] * sum_{k<=s} M[t,k] * E[s-k]   -> bf16
// ---------------------------------------------------------------------------
__device__ __forceinline__ uint32_t smem_u32(const void* p) {
    return (uint32_t)__cvta_generic_to_shared(p);
}
__device__ __forceinline__ void cp16(uint32_t dst, const void* src) {
    asm volatile("cp.async.ca.shared.global [%0], [%1], 16;\n" :: "r"(dst), "l"(src));
}

__global__ __launch_bounds__(256, 2) void k_gemm() {
    int r = blockIdx.x;                            // 0..287
    int k = (r < 144) ? (2 * r) : (2 * (287 - r) + 1);
    int si, off;
    if      (k <   8) { si = 7; off = 0;   }
    else if (k <  24) { si = 6; off = 8;   }
    else if (k <  48) { si = 5; off = 24;  }
    else if (k <  80) { si = 4; off = 48;  }
    else if (k < 120) { si = 3; off = 80;  }
    else if (k < 168) { si = 2; off = 120; }
    else if (k < 224) { si = 1; off = 168; }
    else              { si = 0; off = 224; }
    int m  = k - off;
    int ti = si + (m >> 3);
    int b  = m & 7;
    int t0 = ti * 128;
    int s0 = si * 128;

    __shared__ __align__(16) unsigned char Ab[2][128 * 64];   // 16 KB
    __shared__ __align__(16) unsigned char Bb[2][32 * 256];   // 16 KB
    __shared__ __nv_bfloat16 sE[TT];                          // 2 KB
    __shared__ float sSinv[128];

    int tid  = threadIdx.x;
    int wid  = tid >> 5;
    int lane = tid & 31;
    int m_base = (wid >> 1) * 32;
    int n_base = (wid & 1) * 64;

    {
        const uint2* esrc = (const uint2*)g_Ebf;
        uint2* edst = (uint2*)sE;
        for (int i = tid; i < TT / 4; i += 256) edst[i] = esrc[i];
        if (tid < 128) sSinv[tid] = g_Sinv[s0 + tid];
    }

    float acc[2][8][4];
#pragma unroll
    for (int mi = 0; mi < 2; mi++)
#pragma unroll
        for (int nj = 0; nj < 8; nj++)
#pragma unroll
            for (int q = 0; q < 4; q++) acc[mi][nj][q] = 0.0f;

    int a_row = tid >> 1;
    int a_v0  = (tid & 1) * 2;
    int b_k   = tid >> 4;
    int b_vn  = tid & 15;
    int nsteps = (s0 + 128) >> 5;         // TK=32

    auto issueA = [&](int stage, int k0) {
#pragma unroll
        for (int vv = 0; vv < 2; vv++) {
            int v = a_v0 + vv;
            uint32_t dst = smem_u32(Ab[stage] + a_row * 64 + ((v ^ (a_row & 3)) * 16));
            cp16(dst, &g_M[b][t0 + a_row][k0 + v * 8]);
        }
        asm volatile("cp.async.commit_group;\n");
    };
    auto issueB = [&](int stage, int k0) {
#pragma unroll
        for (int rr2 = 0; rr2 < 2; rr2++) {
            int rr = b_k + rr2 * 16;
            union { __nv_bfloat16 h[8]; uint4 u; } pk;
            int dbase = (s0 + b_vn * 8) - (k0 + rr);
#pragma unroll
            for (int j = 0; j < 8; j++) {
                int d = dbase + j;
                pk.h[j] = (d >= 0) ? sE[d] : __float2bfloat16(0.0f);
            }
            *(uint4*)(Bb[stage] + rr * 256 + ((b_vn ^ (rr & 7)) * 16)) = pk.u;
        }
    };

    __syncthreads();
    issueA(0, 0);
    issueB(0, 0);

    for (int step = 0; step < nsteps; step++) {
        int stage = step & 1;
        asm volatile("cp.async.wait_group 0;\n");
        __syncthreads();

        if (step + 1 < nsteps) {
            issueA(stage ^ 1, (step + 1) * 32);
            issueB(stage ^ 1, (step + 1) * 32);
        }

#pragma unroll
        for (int kc = 0; kc < 32; kc += 16) {
            uint32_t afr[2][4];
#pragma unroll
            for (int mi = 0; mi < 2; mi++) {
                int row = m_base + mi * 16 + (lane & 15);
                int v   = (kc >> 3) + (lane >> 4);
                uint32_t addr = smem_u32(Ab[stage] + row * 64 + ((v ^ (row & 3)) * 16));
                asm volatile("ldmatrix.sync.aligned.m8n8.x4.shared.b16 {%0,%1,%2,%3}, [%4];"
                             : "=r"(afr[mi][0]), "=r"(afr[mi][1]),
                               "=r"(afr[mi][2]), "=r"(afr[mi][3])
                             : "r"(addr));
            }
            uint32_t bfr[8][2];
#pragma unroll
            for (int nj2 = 0; nj2 < 4; nj2++) {
                int nvec = (n_base >> 3) + nj2 * 2 + (lane >> 4);
                int krow = kc + (lane & 15);
                uint32_t addr = smem_u32(Bb[stage] + krow * 256 + ((nvec ^ (krow & 7)) * 16));
                uint32_t q0, q1, q2, q3;
                asm volatile("ldmatrix.sync.aligned.m8n8.x4.trans.shared.b16 {%0,%1,%2,%3}, [%4];"
                             : "=r"(q0), "=r"(q1), "=r"(q2), "=r"(q3)
                             : "r"(addr));
                bfr[nj2 * 2 + 0][0] = q0; bfr[nj2 * 2 + 0][1] = q1;
                bfr[nj2 * 2 + 1][0] = q2; bfr[nj2 * 2 + 1][1] = q3;
            }
#pragma unroll
            for (int mi = 0; mi < 2; mi++)
#pragma unroll
                for (int nj = 0; nj < 8; nj++) {
                    asm volatile(
                        "mma.sync.aligned.m16n8k16.row.col.f32.bf16.bf16.f32 "
                        "{%0,%1,%2,%3}, {%4,%5,%6,%7}, {%8,%9}, {%0,%1,%2,%3};"
                        : "+f"(acc[mi][nj][0]), "+f"(acc[mi][nj][1]),
                          "+f"(acc[mi][nj][2]), "+f"(acc[mi][nj][3])
                        : "r"(afr[mi][0]), "r"(afr[mi][1]), "r"(afr[mi][2]), "r"(afr[mi][3]),
                          "r"(bfr[nj][0]), "r"(bfr[nj][1]));
                }
        }
    }

    // m16n8k16 D-fragment: c0,c1 -> (row, col/col+1); c2,c3 -> (row+8, col/col+1)
#pragma unroll
    for (int mi = 0; mi < 2; mi++) {
#pragma unroll
        for (int nj = 0; nj < 8; nj++) {
            int row0 = m_base + mi * 16 + (lane >> 2);
            int col  = n_base + nj * 8 + (lane & 3) * 2;
            float si0 = sSinv[col];
            float si1 = sSinv[col + 1];
            __nv_bfloat162 h0 = __floats2bfloat162_rn(acc[mi][nj][0] * si0,
                                                      acc[mi][nj][1] * si1);
            __nv_bfloat162 h1 = __floats2bfloat162_rn(acc[mi][nj][2] * si0,
                                                      acc[mi][nj][3] * si1);
            *(__nv_bfloat162*)&g_a2h[b][t0 + row0][s0 + col]     = h0;
            *(__nv_bfloat162*)&g_a2h[b][t0 + row0 + 8][s0 + col] = h1;
        }
    }
}

// ---------------------------------------------------------------------------
// Kernel 3: softmax + scatter. 128 threads, ONE row per block, 8KB smem ->
// 16 blocks/SM. idx from gmem; 2 barriers total.
// ---------------------------------------------------------------------------
__device__ __forceinline__ float exp_poly(float x) {
    return 1.0f + x * (1.0f + x * (0.5f + x * (0.16666667f + x * 0.041666667f)));
}

__global__ __launch_bounds__(128) void k_out(const int* __restrict__ idx,
                                             float* __restrict__ out) {
    int b   = blockIdx.y;
    int t   = blockIdx.x;
    int n   = t + 1;
    int tid = threadIdx.x;

    __shared__ float sacc[VV];            // 8 KB
    __shared__ float sred[4];

    // zero accumulator (128 thr x 4 float4)
    float4* z = (float4*)sacc;
#pragma unroll
    for (int j = 0; j < 4; j++) z[tid + j * 128] = make_float4(0.f, 0.f, 0.f, 0.f);

    // exp of 8 consecutive row elements into registers + sum
    const __nv_bfloat16* row = &g_a2h[b][t][0];
    int base = tid * 8;
    float pv[8];
    float sum = 0.0f;
    if (base < n) {
        union { __nv_bfloat162 h2[4]; uint4 u; } ld;
        ld.u = *(const uint4*)(row + base);
#pragma unroll
        for (int j = 0; j < 4; j++) {
            float2 f = __bfloat1622float2(ld.h2[j]);
            int s0 = base + 2 * j, s1 = s0 + 1;
            float e0 = (s0 < n) ? exp_poly(f.x) : 0.0f;
            float e1 = (s1 < n) ? exp_poly(f.y) : 0.0f;
            pv[2 * j] = e0; pv[2 * j + 1] = e1;
            sum += e0 + e1;
        }
    } else {
#pragma unroll
        for (int j = 0; j < 8; j++) pv[j] = 0.0f;
    }
#pragma unroll
    for (int off = 16; off > 0; off >>= 1)
        sum += __shfl_xor_sync(0xffffffff, sum, off);
    if ((tid & 31) == 0) sred[tid >> 5] = sum;
    __syncthreads();                      // sred ready AND sacc zero visible
    float inv = 1.0f / (sred[0] + sred[1] + sred[2] + sred[3]);

    if (base < n) {
        const int4* ig = (const int4*)(idx + b * TT);
        int4 iv0 = ig[tid * 2];
        int4 iv1 = ig[tid * 2 + 1];
        int iv[8] = {iv0.x, iv0.y, iv0.z, iv0.w, iv1.x, iv1.y, iv1.z, iv1.w};
#pragma unroll
        for (int j = 0; j < 8; j++) {
            if (base + j < n) atomicAdd(&sacc[iv[j]], pv[j] * inv);
        }
    }
    __syncthreads();

    // write output row (128 thr x 4 float4 = 2048 floats)
    float4* dst = (float4*)(out + ((size_t)(b * TT + t)) * VV);
    const float4* srcp = (const float4*)sacc;
#pragma unroll
    for (int j = 0; j < 4; j++) dst[tid + j * 128] = srcp[tid + j * 128];
}

// ---------------------------------------------------------------------------
extern "C" void kernel_launch(void* const* d_in, const int* in_sizes, int n_in,
                              void* d_out, int out_size) {
    const int*   idx = nullptr;
    const float* vw  = nullptr;
    const float* W   = nullptr;
    for (int i = 0; i < n_in; i++) {
        if (in_sizes[i] == BB * TT)       idx = (const int*)d_in[i];
        else if (in_sizes[i] == TT)       vw  = (const float*)d_in[i];
        else if (in_sizes[i] == VV * VV)  W   = (const float*)d_in[i];
    }
    float* out = (float*)d_out;

    dim3 gGather(TT, BB);
    k_gather<<<gGather, 128>>>(idx, W, vw);

    k_gemm<<<288, 256>>>();

    dim3 gOut(TT, BB);
    k_out<<<gOut, 128>>>(idx, out);
}

// round 17
// speedup vs baseline: 1.4475x; 1.1106x over previous
#include <cuda_runtime.h>
#include <cuda_bf16.h>
#include <math.h>
#include <stdint.h>

#define BB 8
#define TT 1024
#define VV 2048

// Scratch (__device__ globals: allocation-free rule)
__device__ __nv_bfloat16 g_Ebf[TT];            // bf16-rounded exp(vw[d])
__device__ float         g_Sinv[TT];           // 1 / prefix_sum(round_bf16(exp(vw)))
__device__ __nv_bfloat16 g_M[BB][TT][TT];      // bf16(W[idx_t][idx_s'])   (16MB)
__device__ __nv_bfloat16 g_a2h[BB][TT][TT];    // pre-softmax scores, bf16 (16MB)

__device__ __forceinline__ uint32_t smem_u32(const void* p) {
    return (uint32_t)__cvta_generic_to_shared(p);
}
__device__ __forceinline__ void mbar_init(uint32_t mbar, uint32_t cnt) {
    asm volatile("mbarrier.init.shared.b64 [%0], %1;" :: "r"(mbar), "r"(cnt) : "memory");
}
__device__ __forceinline__ void mbar_expect_tx(uint32_t mbar, uint32_t bytes) {
    asm volatile("mbarrier.arrive.expect_tx.shared.b64 _, [%0], %1;"
                 :: "r"(mbar), "r"(bytes) : "memory");
}
__device__ __forceinline__ void mbar_wait(uint32_t mbar, uint32_t phase) {
    uint32_t done = 0;
    while (!done) {
        asm volatile("{\n\t.reg .pred p;\n\t"
                     "mbarrier.try_wait.parity.shared::cta.b64 p, [%1], %2;\n\t"
                     "selp.b32 %0, 1, 0, p;\n\t}"
                     : "=r"(done) : "r"(mbar), "r"(phase) : "memory");
    }
}
__device__ __forceinline__ void bulk_g2s(uint32_t dst_smem, const void* src, uint32_t bytes,
                                         uint32_t mbar) {
    asm volatile("cp.async.bulk.shared::cta.global.mbarrier::complete_tx::bytes "
                 "[%0], [%1], %2, [%3];"
                 :: "r"(dst_smem), "l"(src), "r"(bytes), "r"(mbar) : "memory");
}
__device__ __forceinline__ void bulk_s2g(void* dst, uint32_t src_smem, uint32_t bytes) {
    asm volatile("cp.async.bulk.global.shared::cta.bulk_group [%0], [%1], %2;"
                 :: "l"(dst), "r"(src_smem), "r"(bytes) : "memory");
}

// ---------------------------------------------------------------------------
// Kernel 1: gather M[b][t][s'] = bf16(W[idx[b,t]][idx[b,s']]).
// 128 threads, one row per block. W row staged via ONE cp.async.bulk (8KB).
// Block (0,0) also computes E/Sinv (overlaps the bulk copy).
// ---------------------------------------------------------------------------
__global__ __launch_bounds__(128) void k_gather(const int* __restrict__ idx,
                                                const float* __restrict__ W,
                                                const float* __restrict__ vw) {
    int b   = blockIdx.y;
    int t   = blockIdx.x;
    int tid = threadIdx.x;

    __shared__ __align__(16) float row[VV];   // 8 KB
    __shared__ __align__(8) unsigned long long mbar_s;
    __shared__ float wsum[4];

    uint32_t mbar = smem_u32(&mbar_s);
    if (tid == 0) mbar_init(mbar, 1);
    __syncthreads();
    if (tid == 0) {
        int wr = idx[b * TT + t];
        mbar_expect_tx(mbar, VV * 4);
        bulk_g2s(smem_u32(row), W + (size_t)wr * VV, VV * 4, mbar);
    }

    // ---- prefix fold: only block (0,0); overlaps the bulk copy ----
    if (blockIdx.x == 0 && blockIdx.y == 0) {
        int lane = tid & 31, wid = tid >> 5;
        int i0 = tid * 8;
        float4 va = *(const float4*)(vw + i0);
        float4 vb = *(const float4*)(vw + i0 + 4);
        float xs[8] = {va.x, va.y, va.z, va.w, vb.x, vb.y, vb.z, vb.w};
        __nv_bfloat16 eb[8];
        float c[8];
        float run = 0.0f;
#pragma unroll
        for (int j = 0; j < 8; j++) {
            eb[j] = __float2bfloat16(expf(xs[j]));
            run += __bfloat162float(eb[j]);
            c[j] = run;
        }
        union { __nv_bfloat16 h[8]; uint4 u; } pe;
#pragma unroll
        for (int j = 0; j < 8; j++) pe.h[j] = eb[j];
        *(uint4*)&g_Ebf[i0] = pe.u;

        float sv = run;
#pragma unroll
        for (int o = 1; o < 32; o <<= 1) {
            float y = __shfl_up_sync(0xffffffff, sv, o);
            if (lane >= o) sv += y;
        }
        float warpExcl = sv - run;
        if (lane == 31) wsum[wid] = sv;
        __syncthreads();
        if (wid == 0 && lane < 4) {
            float v4 = wsum[lane];
#pragma unroll
            for (int o = 1; o < 4; o <<= 1) {
                float y = __shfl_up_sync(0xf, v4, o);
                if (lane >= o) v4 += y;
            }
            wsum[lane] = v4;
        }
        __syncthreads();
        float base = ((wid > 0) ? wsum[wid - 1] : 0.0f) + warpExcl;
#pragma unroll
        for (int j = 0; j < 8; j++) g_Sinv[i0 + j] = 1.0f / (base + c[j]);
    }

    mbar_wait(mbar, 0);                   // W row resident in smem

    // gather 8 consecutive outputs per thread; idx from gmem (int4 x2)
    int p0 = tid * 8;
    const int4* ig = (const int4*)(idx + b * TT);
    int4 iv0 = ig[tid * 2];
    int4 iv1 = ig[tid * 2 + 1];
    union { __nv_bfloat162 h2[4]; uint4 u; } pk;
    pk.h2[0] = __floats2bfloat162_rn(row[iv0.x], row[iv0.y]);
    pk.h2[1] = __floats2bfloat162_rn(row[iv0.z], row[iv0.w]);
    pk.h2[2] = __floats2bfloat162_rn(row[iv1.x], row[iv1.y]);
    pk.h2[3] = __floats2bfloat162_rn(row[iv1.z], row[iv1.w]);
    *(uint4*)&g_M[b][t][p0] = pk.u;
}

// ---------------------------------------------------------------------------
// Kernel 2: bf16 tensor-core GEMM (R10/R15 version, verbatim).
//   a2[b][t][s] = Sinv[s] * sum_{k<=s} M[t,k] * E[s-k]   -> bf16
// ---------------------------------------------------------------------------
__device__ __forceinline__ void cp16(uint32_t dst, const void* src) {
    asm volatile("cp.async.ca.shared.global [%0], [%1], 16;\n" :: "r"(dst), "l"(src));
}

__global__ __launch_bounds__(256, 2) void k_gemm() {
    int r = blockIdx.x;                            // 0..287
    int k = (r < 144) ? (2 * r) : (2 * (287 - r) + 1);
    int si, off;
    if      (k <   8) { si = 7; off = 0;   }
    else if (k <  24) { si = 6; off = 8;   }
    else if (k <  48) { si = 5; off = 24;  }
    else if (k <  80) { si = 4; off = 48;  }
    else if (k < 120) { si = 3; off = 80;  }
    else if (k < 168) { si = 2; off = 120; }
    else if (k < 224) { si = 1; off = 168; }
    else              { si = 0; off = 224; }
    int m  = k - off;
    int ti = si + (m >> 3);
    int b  = m & 7;
    int t0 = ti * 128;
    int s0 = si * 128;

    __shared__ __align__(16) unsigned char Ab[2][128 * 64];   // 16 KB
    __shared__ __align__(16) unsigned char Bb[2][32 * 256];   // 16 KB
    __shared__ __nv_bfloat16 sE[TT];                          // 2 KB
    __shared__ float sSinv[128];

    int tid  = threadIdx.x;
    int wid  = tid >> 5;
    int lane = tid & 31;
    int m_base = (wid >> 1) * 32;
    int n_base = (wid & 1) * 64;

    {
        const uint2* esrc = (const uint2*)g_Ebf;
        uint2* edst = (uint2*)sE;
        for (int i = tid; i < TT / 4; i += 256) edst[i] = esrc[i];
        if (tid < 128) sSinv[tid] = g_Sinv[s0 + tid];
    }

    float acc[2][8][4];
#pragma unroll
    for (int mi = 0; mi < 2; mi++)
#pragma unroll
        for (int nj = 0; nj < 8; nj++)
#pragma unroll
            for (int q = 0; q < 4; q++) acc[mi][nj][q] = 0.0f;

    int a_row = tid >> 1;
    int a_v0  = (tid & 1) * 2;
    int b_k   = tid >> 4;
    int b_vn  = tid & 15;
    int nsteps = (s0 + 128) >> 5;         // TK=32

    auto issueA = [&](int stage, int k0) {
#pragma unroll
        for (int vv = 0; vv < 2; vv++) {
            int v = a_v0 + vv;
            uint32_t dst = smem_u32(Ab[stage] + a_row * 64 + ((v ^ (a_row & 3)) * 16));
            cp16(dst, &g_M[b][t0 + a_row][k0 + v * 8]);
        }
        asm volatile("cp.async.commit_group;\n");
    };
    auto issueB = [&](int stage, int k0) {
#pragma unroll
        for (int rr2 = 0; rr2 < 2; rr2++) {
            int rr = b_k + rr2 * 16;
            union { __nv_bfloat16 h[8]; uint4 u; } pk;
            int dbase = (s0 + b_vn * 8) - (k0 + rr);
#pragma unroll
            for (int j = 0; j < 8; j++) {
                int d = dbase + j;
                pk.h[j] = (d >= 0) ? sE[d] : __float2bfloat16(0.0f);
            }
            *(uint4*)(Bb[stage] + rr * 256 + ((b_vn ^ (rr & 7)) * 16)) = pk.u;
        }
    };

    __syncthreads();
    issueA(0, 0);
    issueB(0, 0);

    for (int step = 0; step < nsteps; step++) {
        int stage = step & 1;
        asm volatile("cp.async.wait_group 0;\n");
        __syncthreads();

        if (step + 1 < nsteps) {
            issueA(stage ^ 1, (step + 1) * 32);
            issueB(stage ^ 1, (step + 1) * 32);
        }

#pragma unroll
        for (int kc = 0; kc < 32; kc += 16) {
            uint32_t afr[2][4];
#pragma unroll
            for (int mi = 0; mi < 2; mi++) {
                int row = m_base + mi * 16 + (lane & 15);
                int v   = (kc >> 3) + (lane >> 4);
                uint32_t addr = smem_u32(Ab[stage] + row * 64 + ((v ^ (row & 3)) * 16));
                asm volatile("ldmatrix.sync.aligned.m8n8.x4.shared.b16 {%0,%1,%2,%3}, [%4];"
                             : "=r"(afr[mi][0]), "=r"(afr[mi][1]),
                               "=r"(afr[mi][2]), "=r"(afr[mi][3])
                             : "r"(addr));
            }
            uint32_t bfr[8][2];
#pragma unroll
            for (int nj2 = 0; nj2 < 4; nj2++) {
                int nvec = (n_base >> 3) + nj2 * 2 + (lane >> 4);
                int krow = kc + (lane & 15);
                uint32_t addr = smem_u32(Bb[stage] + krow * 256 + ((nvec ^ (krow & 7)) * 16));
                uint32_t q0, q1, q2, q3;
                asm volatile("ldmatrix.sync.aligned.m8n8.x4.trans.shared.b16 {%0,%1,%2,%3}, [%4];"
                             : "=r"(q0), "=r"(q1), "=r"(q2), "=r"(q3)
                             : "r"(addr));
                bfr[nj2 * 2 + 0][0] = q0; bfr[nj2 * 2 + 0][1] = q1;
                bfr[nj2 * 2 + 1][0] = q2; bfr[nj2 * 2 + 1][1] = q3;
            }
#pragma unroll
            for (int mi = 0; mi < 2; mi++)
#pragma unroll
                for (int nj = 0; nj < 8; nj++) {
                    asm volatile(
                        "mma.sync.aligned.m16n8k16.row.col.f32.bf16.bf16.f32 "
                        "{%0,%1,%2,%3}, {%4,%5,%6,%7}, {%8,%9}, {%0,%1,%2,%3};"
                        : "+f"(acc[mi][nj][0]), "+f"(acc[mi][nj][1]),
                          "+f"(acc[mi][nj][2]), "+f"(acc[mi][nj][3])
                        : "r"(afr[mi][0]), "r"(afr[mi][1]), "r"(afr[mi][2]), "r"(afr[mi][3]),
                          "r"(bfr[nj][0]), "r"(bfr[nj][1]));
                }
        }
    }

    // m16n8k16 D-fragment: c0,c1 -> (row, col/col+1); c2,c3 -> (row+8, col/col+1)
#pragma unroll
    for (int mi = 0; mi < 2; mi++) {
#pragma unroll
        for (int nj = 0; nj < 8; nj++) {
            int row0 = m_base + mi * 16 + (lane >> 2);
            int col  = n_base + nj * 8 + (lane & 3) * 2;
            float si0 = sSinv[col];
            float si1 = sSinv[col + 1];
            __nv_bfloat162 h0 = __floats2bfloat162_rn(acc[mi][nj][0] * si0,
                                                      acc[mi][nj][1] * si1);
            __nv_bfloat162 h1 = __floats2bfloat162_rn(acc[mi][nj][2] * si0,
                                                      acc[mi][nj][3] * si1);
            *(__nv_bfloat162*)&g_a2h[b][t0 + row0][s0 + col]     = h0;
            *(__nv_bfloat162*)&g_a2h[b][t0 + row0 + 8][s0 + col] = h1;
        }
    }
}

// ---------------------------------------------------------------------------
// Kernel 3: softmax + scatter. 128 threads, one row per block.
// Output row stored via ONE cp.async.bulk shared->global (8KB).
// ---------------------------------------------------------------------------
__device__ __forceinline__ float exp_poly(float x) {
    return 1.0f + x * (1.0f + x * (0.5f + x * (0.16666667f + x * 0.041666667f)));
}

__global__ __launch_bounds__(128) void k_out(const int* __restrict__ idx,
                                             float* __restrict__ out) {
    int b   = blockIdx.y;
    int t   = blockIdx.x;
    int n   = t + 1;
    int tid = threadIdx.x;

    __shared__ __align__(16) float sacc[VV];  // 8 KB
    __shared__ float sred[4];

    // zero accumulator (128 thr x 4 float4)
    float4* z = (float4*)sacc;
#pragma unroll
    for (int j = 0; j < 4; j++) z[tid + j * 128] = make_float4(0.f, 0.f, 0.f, 0.f);

    // exp of 8 consecutive row elements into registers + sum
    const __nv_bfloat16* row = &g_a2h[b][t][0];
    int base = tid * 8;
    float pv[8];
    float sum = 0.0f;
    if (base < n) {
        union { __nv_bfloat162 h2[4]; uint4 u; } ld;
        ld.u = *(const uint4*)(row + base);
#pragma unroll
        for (int j = 0; j < 4; j++) {
            float2 f = __bfloat1622float2(ld.h2[j]);
            int s0 = base + 2 * j, s1 = s0 + 1;
            float e0 = (s0 < n) ? exp_poly(f.x) : 0.0f;
            float e1 = (s1 < n) ? exp_poly(f.y) : 0.0f;
            pv[2 * j] = e0; pv[2 * j + 1] = e1;
            sum += e0 + e1;
        }
    } else {
#pragma unroll
        for (int j = 0; j < 8; j++) pv[j] = 0.0f;
    }
#pragma unroll
    for (int off = 16; off > 0; off >>= 1)
        sum += __shfl_xor_sync(0xffffffff, sum, off);
    if ((tid & 31) == 0) sred[tid >> 5] = sum;
    __syncthreads();                      // sred ready AND sacc zero visible
    float inv = 1.0f / (sred[0] + sred[1] + sred[2] + sred[3]);

    if (base < n) {
        const int4* ig = (const int4*)(idx + b * TT);
        int4 iv0 = ig[tid * 2];
        int4 iv1 = ig[tid * 2 + 1];
        int iv[8] = {iv0.x, iv0.y, iv0.z, iv0.w, iv1.x, iv1.y, iv1.z, iv1.w};
#pragma unroll
        for (int j = 0; j < 8; j++) {
            if (base + j < n) atomicAdd(&sacc[iv[j]], pv[j] * inv);
        }
    }
    __syncthreads();

    // bulk store of the output row (one op, replaces 4 STG.128/thread)
    if (tid == 0) {
        asm volatile("fence.proxy.async.shared::cta;" ::: "memory");
        bulk_s2g(out + ((size_t)(b * TT + t)) * VV, smem_u32(sacc), VV * 4);
        asm volatile("cp.async.bulk.commit_group;" ::: "memory");
        asm volatile("cp.async.bulk.wait_group.read 0;" ::: "memory");
    }
    __syncthreads();                      // smem must outlive the bulk read
}

// ---------------------------------------------------------------------------
extern "C" void kernel_launch(void* const* d_in, const int* in_sizes, int n_in,
                              void* d_out, int out_size) {
    const int*   idx = nullptr;
    const float* vw  = nullptr;
    const float* W   = nullptr;
    for (int i = 0; i < n_in; i++) {
        if (in_sizes[i] == BB * TT)       idx = (const int*)d_in[i];
        else if (in_sizes[i] == TT)       vw  = (const float*)d_in[i];
        else if (in_sizes[i] == VV * VV)  W   = (const float*)d_in[i];
    }
    float* out = (float*)d_out;

    dim3 gGather(TT, BB);
    k_gather<<<gGather, 128>>>(idx, W, vw);

    k_gemm<<<288, 256>>>();

    dim3 gOut(TT, BB);
    k_out<<<gOut, 128>>>(idx, out);
}